// round 1
// baseline (speedup 1.0000x reference)
#include <cuda_runtime.h>

#define NS 512   // samples
#define DE 512   // embedding dim
#define NC 5     // classes

// ---------------- device scratch (no allocation allowed) ----------------
__device__ float g_rn[NS];        // 1/row_norm
__device__ float g_cos[NS * NS];  // pairwise cosine
__device__ float g_cp[NS];        // class position per sample
__device__ float g_invneg[NS];    // 1 / max(negcount_i, 1)
__device__ float g_sum;
__device__ int   g_nz;

// ---------------- kernel 1: class positions, histogram, zero accumulators
__global__ void prep_kernel(const float* __restrict__ dist_raw,
                            const int* __restrict__ target) {
    __shared__ float cls_pos[NC];
    __shared__ int counts[NC];
    int t = threadIdx.x;  // 512 threads
    if (t < NC) counts[t] = 0;
    if (t == 0) {
        float c = 0.f;
        cls_pos[0] = 0.f;
        #pragma unroll
        for (int i = 0; i < NC - 1; i++) {
            c += log1pf(expf(dist_raw[i]));  // softplus, cumsum
            cls_pos[i + 1] = c;
        }
        g_sum = 0.f;
        g_nz = 0;
    }
    __syncthreads();
    int tg = target[t];
    atomicAdd(&counts[tg], 1);
    __syncthreads();
    g_cp[t] = cls_pos[tg];
    int neg = NS - counts[tg];
    g_invneg[t] = 1.0f / (float)(neg > 1 ? neg : 1);
}

// ---------------- kernel 2: reciprocal row norms ----------------
__global__ void norm_kernel(const float* __restrict__ x) {
    int r = blockIdx.x;
    const float* row = x + (size_t)r * DE;
    float s = 0.f;
    for (int j = threadIdx.x; j < DE; j += 128) {
        float v = row[j];
        s += v * v;
    }
    // reduce over 128 threads (4 warps)
    for (int o = 16; o > 0; o >>= 1) s += __shfl_down_sync(0xffffffffu, s, o);
    __shared__ float ws[4];
    int wid = threadIdx.x >> 5, lid = threadIdx.x & 31;
    if (lid == 0) ws[wid] = s;
    __syncthreads();
    if (threadIdx.x == 0) {
        float tot = ws[0] + ws[1] + ws[2] + ws[3];
        float nrm = sqrtf(tot);
        g_rn[r] = 1.0f / fmaxf(nrm, 1e-8f);
    }
}

// ---------------- kernel 3: cos = (x xT) scaled by rn_i rn_j ----------------
// 32x32 tile per block, 256 threads, 2x2 per thread
__global__ void gemm_kernel(const float* __restrict__ x) {
    __shared__ float As[32][33];
    __shared__ float Bs[32][33];
    int tx = threadIdx.x & 15;
    int ty = threadIdx.x >> 4;
    int bi = blockIdx.y * 32;
    int bj = blockIdx.x * 32;
    float a00 = 0.f, a01 = 0.f, a10 = 0.f, a11 = 0.f;
    for (int k0 = 0; k0 < DE; k0 += 32) {
        for (int l = threadIdx.x; l < 32 * 32; l += 256) {
            int r = l >> 5, c = l & 31;
            As[r][c] = x[(size_t)(bi + r) * DE + k0 + c];
            Bs[r][c] = x[(size_t)(bj + r) * DE + k0 + c];
        }
        __syncthreads();
        #pragma unroll
        for (int kk = 0; kk < 32; kk++) {
            float ra0 = As[ty * 2][kk];
            float ra1 = As[ty * 2 + 1][kk];
            float rb0 = Bs[tx * 2][kk];
            float rb1 = Bs[tx * 2 + 1][kk];
            a00 += ra0 * rb0; a01 += ra0 * rb1;
            a10 += ra1 * rb0; a11 += ra1 * rb1;
        }
        __syncthreads();
    }
    int i0 = bi + ty * 2, j0 = bj + tx * 2;
    float ri0 = g_rn[i0], ri1 = g_rn[i0 + 1];
    float rj0 = g_rn[j0], rj1 = g_rn[j0 + 1];
    g_cos[(size_t)i0 * NS + j0]           = a00 * ri0 * rj0;
    g_cos[(size_t)i0 * NS + j0 + 1]       = a01 * ri0 * rj1;
    g_cos[(size_t)(i0 + 1) * NS + j0]     = a10 * ri1 * rj0;
    g_cos[(size_t)(i0 + 1) * NS + j0 + 1] = a11 * ri1 * rj1;
}

// ---------------- kernel 4: per-anchor loss accumulation ----------------
// one block per anchor i, 256 threads
__global__ void loss_kernel() {
    __shared__ float bvals[NS];   // cos[i,j] + margin, or -1e30 for non-negatives
    __shared__ float crow[NS];
    __shared__ float cps[NS];
    __shared__ int klist[NS];
    __shared__ int kcnt;
    __shared__ float red_s[8];
    __shared__ int red_n[8];

    int i = blockIdx.x;
    int t = threadIdx.x;
    if (t == 0) kcnt = 0;
    for (int j = t; j < NS; j += 256) {
        crow[j] = g_cos[(size_t)i * NS + j];
        cps[j] = g_cp[j];
    }
    __syncthreads();
    float cpi = cps[i];

    // negatives: b[j] = cos[i,j] + |cp_i - cp_j|; others masked hard-negative
    // positives: same class position, k != i -> compact list
    for (int j = t; j < NS; j += 256) {
        float m = fabsf(cpi - cps[j]);
        bvals[j] = (m != 0.0f) ? (crow[j] + m) : -1e30f;
        if (m == 0.0f && j != i) {
            int p = atomicAdd(&kcnt, 1);
            klist[p] = j;
        }
    }
    __syncthreads();

    int nk = kcnt;
    float inv = g_invneg[i];
    float lsum = 0.f;
    int lnz = 0;
    for (int p = t; p < nk; p += 256) {
        float cik = crow[klist[p]];
        float acc = 0.f;
        #pragma unroll 8
        for (int j = 0; j < NS; j++) {
            acc += fmaxf(bvals[j] - cik, 0.0f);
        }
        lsum += acc * inv;
        lnz += (acc > 0.f) ? 1 : 0;
    }

    // block reduce (8 warps)
    for (int o = 16; o > 0; o >>= 1) {
        lsum += __shfl_down_sync(0xffffffffu, lsum, o);
        lnz += __shfl_down_sync(0xffffffffu, lnz, o);
    }
    int wid = t >> 5, lid = t & 31;
    if (lid == 0) { red_s[wid] = lsum; red_n[wid] = lnz; }
    __syncthreads();
    if (t == 0) {
        float bs = 0.f; int bn = 0;
        #pragma unroll
        for (int w = 0; w < 8; w++) { bs += red_s[w]; bn += red_n[w]; }
        if (bn > 0 || bs != 0.f) {
            atomicAdd(&g_sum, bs);
            atomicAdd(&g_nz, bn);
        }
    }
}

// ---------------- kernel 5: finalize ----------------
__global__ void fin_kernel(float* __restrict__ out) {
    int nz = g_nz;
    out[0] = g_sum / (float)(nz > 1 ? nz : 1);
}

extern "C" void kernel_launch(void* const* d_in, const int* in_sizes, int n_in,
                              void* d_out, int out_size) {
    const float* pred = (const float*)d_in[0];   // [512, 512] f32
    const float* draw = (const float*)d_in[1];   // [4] f32
    const int* target = (const int*)d_in[2];     // [512] i32
    float* out = (float*)d_out;

    prep_kernel<<<1, NS>>>(draw, target);
    norm_kernel<<<NS, 128>>>(pred);
    gemm_kernel<<<dim3(16, 16), 256>>>(pred);
    loss_kernel<<<NS, 256>>>();
    fin_kernel<<<1, 1>>>(out);
}

// round 4
// speedup vs baseline: 1.1462x; 1.1462x over previous
#include <cuda_runtime.h>

#define NS 512   // samples
#define DE 512   // embedding dim
#define NC 5     // classes

// ---------------- device scratch (no allocation allowed) ----------------
__device__ float g_cos[NS * NS];  // pairwise cosine
__device__ float g_psum[NS];      // per-anchor partial loss sum
__device__ int   g_pnz[NS];       // per-anchor nonzero count

// ---------------- f32x2 packed helpers (sm_103a) ----------------
__device__ __forceinline__ unsigned long long dupf(float a) {
    unsigned long long d;
    asm("mov.b64 %0, {%1, %1};" : "=l"(d) : "f"(a));
    return d;
}
__device__ __forceinline__ unsigned long long fma2(unsigned long long a,
                                                   unsigned long long b,
                                                   unsigned long long c) {
    unsigned long long d;
    asm("fma.rn.f32x2 %0, %1, %2, %3;" : "=l"(d) : "l"(a), "l"(b), "l"(c));
    return d;
}
__device__ __forceinline__ float2 unpk(unsigned long long v) {
    float2 r;
    asm("mov.b64 {%0, %1}, %2;" : "=f"(r.x), "=f"(r.y) : "l"(v));
    return r;
}

// ---------------- kernel 1: fused norms + cosine GEMM ----------------
// 32x32 output tile, 64 threads, 4x4 micro-tile, packed f32x2 FMA.
// Row 1/norms computed on the fly from streamed tiles (fused norm kernel).
__global__ void __launch_bounds__(64) gemm_kernel(const float* __restrict__ x) {
    __shared__ __align__(16) float As[32][36];  // [k][row], stride 36 floats (16B-aligned rows)
    __shared__ __align__(16) float Bs[32][36];
    __shared__ float rnA[32], rnB[32];

    int t = threadIdx.x;           // 0..63
    int bi = blockIdx.y * 32;
    int bj = blockIdx.x * 32;
    int tx = t & 7, ty = t >> 3;   // 8x8 micro grid
    int lrow = t >> 1;             // 0..31 : row this thread loads
    int lsel = t & 1;              // which interleaved float4 set

    float sa = 0.f, sb = 0.f;      // row sum-of-squares (A row, B row)
    unsigned long long acc[4][2];
    #pragma unroll
    for (int r = 0; r < 4; r++) { acc[r][0] = 0ull; acc[r][1] = 0ull; }

    for (int k0 = 0; k0 < DE; k0 += 32) {
        // each thread loads 4 float4 of A and B: float4 ids {lsel + 2q}
        float4 a[4], b[4];
        const float4* gA = (const float4*)(x + (size_t)(bi + lrow) * DE + k0);
        const float4* gB = (const float4*)(x + (size_t)(bj + lrow) * DE + k0);
        #pragma unroll
        for (int q = 0; q < 4; q++) {
            a[q] = gA[lsel + 2 * q];
            b[q] = gB[lsel + 2 * q];
        }
        __syncthreads();  // previous tile fully consumed
        #pragma unroll
        for (int q = 0; q < 4; q++) {
            int c = 4 * (lsel + 2 * q);
            As[c + 0][lrow] = a[q].x; As[c + 1][lrow] = a[q].y;
            As[c + 2][lrow] = a[q].z; As[c + 3][lrow] = a[q].w;
            Bs[c + 0][lrow] = b[q].x; Bs[c + 1][lrow] = b[q].y;
            Bs[c + 2][lrow] = b[q].z; Bs[c + 3][lrow] = b[q].w;
            sa += a[q].x * a[q].x + a[q].y * a[q].y + a[q].z * a[q].z + a[q].w * a[q].w;
            sb += b[q].x * b[q].x + b[q].y * b[q].y + b[q].z * b[q].z + b[q].w * b[q].w;
        }
        __syncthreads();
        #pragma unroll
        for (int kk = 0; kk < 32; kk++) {
            float4 av = *(const float4*)&As[kk][4 * ty];
            ulonglong2 bv = *(const ulonglong2*)&Bs[kk][4 * tx];
            unsigned long long a0 = dupf(av.x), a1 = dupf(av.y);
            unsigned long long a2 = dupf(av.z), a3 = dupf(av.w);
            acc[0][0] = fma2(a0, bv.x, acc[0][0]); acc[0][1] = fma2(a0, bv.y, acc[0][1]);
            acc[1][0] = fma2(a1, bv.x, acc[1][0]); acc[1][1] = fma2(a1, bv.y, acc[1][1]);
            acc[2][0] = fma2(a2, bv.x, acc[2][0]); acc[2][1] = fma2(a2, bv.y, acc[2][1]);
            acc[3][0] = fma2(a3, bv.x, acc[3][0]); acc[3][1] = fma2(a3, bv.y, acc[3][1]);
        }
    }

    // combine the two partial sumsq per row (threads 2r, 2r+1)
    sa += __shfl_xor_sync(0xffffffffu, sa, 1);
    sb += __shfl_xor_sync(0xffffffffu, sb, 1);
    if ((t & 1) == 0) {
        rnA[lrow] = rsqrtf(fmaxf(sa, 1e-16f));
        rnB[lrow] = rsqrtf(fmaxf(sb, 1e-16f));
    }
    __syncthreads();

    #pragma unroll
    for (int r = 0; r < 4; r++) {
        float ri = rnA[4 * ty + r];
        float2 p0 = unpk(acc[r][0]);
        float2 p1 = unpk(acc[r][1]);
        float4 o;
        o.x = p0.x * ri * rnB[4 * tx + 0];
        o.y = p0.y * ri * rnB[4 * tx + 1];
        o.z = p1.x * ri * rnB[4 * tx + 2];
        o.w = p1.y * ri * rnB[4 * tx + 3];
        *(float4*)&g_cos[(size_t)(bi + 4 * ty + r) * NS + bj + 4 * tx] = o;
    }
}

// ---------------- kernel 2: per-anchor loss (fused prep) ----------------
// one block per anchor i, 128 threads
__global__ void __launch_bounds__(128) loss_kernel(const float* __restrict__ dist_raw,
                                                   const int* __restrict__ target) {
    __shared__ __align__(16) float bvals[NS];  // cos[i,j]+margin, or -1e30
    __shared__ float crow[NS];
    __shared__ float cps[NS];
    __shared__ int klist[NS];
    __shared__ float cls_pos[NC];
    __shared__ int kcnt, scount;
    __shared__ float red_s[4];
    __shared__ int red_n[4];

    int i = blockIdx.x;
    int t = threadIdx.x;

    if (t == 0) {
        kcnt = 0; scount = 0;
        float c = 0.f;
        cls_pos[0] = 0.f;
        #pragma unroll
        for (int q = 0; q < NC - 1; q++) {
            c += log1pf(expf(dist_raw[q]));  // softplus cumsum
            cls_pos[q + 1] = c;
        }
    }
    __syncthreads();

    for (int j = t; j < NS; j += 128) {
        cps[j] = cls_pos[target[j]];
        crow[j] = g_cos[(size_t)i * NS + j];
    }
    __syncthreads();

    float cpi = cps[i];
    int myc = 0;
    for (int j = t; j < NS; j += 128) {
        float m = fabsf(cpi - cps[j]);
        bool same = (m == 0.0f);  // class_pos strictly increasing -> equality iff same class
        bvals[j] = same ? -1e30f : (crow[j] + m);
        if (same) {
            myc++;
            if (j != i) klist[atomicAdd(&kcnt, 1)] = j;
        }
    }
    atomicAdd(&scount, myc);
    __syncthreads();

    int nk = kcnt;
    int negc = NS - scount;
    float inv = 1.0f / (float)(negc > 1 ? negc : 1);

    float lsum = 0.f;
    int lnz = 0;
    const float4* bv4 = (const float4*)bvals;
    for (int p = t; p < nk; p += 128) {
        float cik = crow[klist[p]];
        float acc0 = 0.f, acc1 = 0.f;
        #pragma unroll 8
        for (int jj = 0; jj < NS / 4; jj++) {
            float4 bv = bv4[jj];
            acc0 += fmaxf(bv.x - cik, 0.f) + fmaxf(bv.y - cik, 0.f);
            acc1 += fmaxf(bv.z - cik, 0.f) + fmaxf(bv.w - cik, 0.f);
        }
        float acc = acc0 + acc1;
        lsum += acc * inv;
        lnz += (acc != 0.f) ? 1 : 0;
    }

    // block reduce (4 warps)
    for (int o = 16; o > 0; o >>= 1) {
        lsum += __shfl_down_sync(0xffffffffu, lsum, o);
        lnz += __shfl_down_sync(0xffffffffu, lnz, o);
    }
    int wid = t >> 5, lid = t & 31;
    if (lid == 0) { red_s[wid] = lsum; red_n[wid] = lnz; }
    __syncthreads();
    if (t == 0) {
        g_psum[i] = red_s[0] + red_s[1] + red_s[2] + red_s[3];
        g_pnz[i] = red_n[0] + red_n[1] + red_n[2] + red_n[3];
    }
}

// ---------------- kernel 3: finalize ----------------
__global__ void __launch_bounds__(NS) fin_kernel(float* __restrict__ out) {
    __shared__ float ws[16];
    __shared__ int wn[16];
    int t = threadIdx.x;  // 512
    float s = g_psum[t];
    int n = g_pnz[t];
    for (int o = 16; o > 0; o >>= 1) {
        s += __shfl_down_sync(0xffffffffu, s, o);
        n += __shfl_down_sync(0xffffffffu, n, o);
    }
    int wid = t >> 5, lid = t & 31;
    if (lid == 0) { ws[wid] = s; wn[wid] = n; }
    __syncthreads();
    if (t == 0) {
        float S = 0.f; int N = 0;
        #pragma unroll
        for (int w = 0; w < 16; w++) { S += ws[w]; N += wn[w]; }
        out[0] = S / (float)(N > 1 ? N : 1);
    }
}

extern "C" void kernel_launch(void* const* d_in, const int* in_sizes, int n_in,
                              void* d_out, int out_size) {
    const float* pred = (const float*)d_in[0];   // [512, 512] f32
    const float* draw = (const float*)d_in[1];   // [4] f32
    const int* target = (const int*)d_in[2];     // [512] i32
    float* out = (float*)d_out;

    gemm_kernel<<<dim3(16, 16), 64>>>(pred);
    loss_kernel<<<NS, 128>>>(draw, target);
    fin_kernel<<<1, NS>>>(out);
}

// round 5
// speedup vs baseline: 1.5991x; 1.3950x over previous
#include <cuda_runtime.h>

#define NS 512   // samples
#define DE 512   // embedding dim
#define NC 5     // classes
#define KSPLIT 4
#define KCHUNK (DE / KSPLIT)   // 128

// ---------------- device scratch (no allocation allowed) ----------------
__device__ float g_part[KSPLIT][NS * NS];  // raw partial dot products (4 MB)
__device__ float g_rn[NS];                 // 1 / max(row_norm, 1e-8)
__device__ float g_psum[NS];               // per-anchor partial loss sum
__device__ int   g_pnz[NS];                // per-anchor nonzero count

// ---------------- f32x2 packed helpers (sm_103a) ----------------
__device__ __forceinline__ unsigned long long dupf(float a) {
    unsigned long long d;
    asm("mov.b64 %0, {%1, %1};" : "=l"(d) : "f"(a));
    return d;
}
__device__ __forceinline__ unsigned long long fma2(unsigned long long a,
                                                   unsigned long long b,
                                                   unsigned long long c) {
    unsigned long long d;
    asm("fma.rn.f32x2 %0, %1, %2, %3;" : "=l"(d) : "l"(a), "l"(b), "l"(c));
    return d;
}
__device__ __forceinline__ float2 unpk(unsigned long long v) {
    float2 r;
    asm("mov.b64 {%0, %1}, %2;" : "=f"(r.x), "=f"(r.y) : "l"(v));
    return r;
}

// ---------------- kernel 1: reciprocal row norms ----------------
__global__ void __launch_bounds__(128) norm_kernel(const float* __restrict__ x) {
    int r = blockIdx.x;
    const float4* row = (const float4*)(x + (size_t)r * DE);
    float s = 0.f;
    for (int j = threadIdx.x; j < DE / 4; j += 128) {
        float4 v = row[j];
        s += v.x * v.x + v.y * v.y + v.z * v.z + v.w * v.w;
    }
    for (int o = 16; o > 0; o >>= 1) s += __shfl_down_sync(0xffffffffu, s, o);
    __shared__ float ws[4];
    int wid = threadIdx.x >> 5, lid = threadIdx.x & 31;
    if (lid == 0) ws[wid] = s;
    __syncthreads();
    if (threadIdx.x == 0) {
        float nrm = sqrtf(ws[0] + ws[1] + ws[2] + ws[3]);
        g_rn[r] = 1.0f / fmaxf(nrm, 1e-8f);
    }
}

// ---------------- kernel 2: partial-K raw dot GEMM ----------------
// 32x32 output tile, 64 threads, 4x4 micro-tile, f32x2 FMA.
// blockIdx.z selects K-chunk [z*128, z*128+128); partial written to g_part[z].
__global__ void __launch_bounds__(64) gemm_kernel(const float* __restrict__ x) {
    __shared__ __align__(16) float As[32][36];  // [k][row]
    __shared__ __align__(16) float Bs[32][36];

    int t = threadIdx.x;           // 0..63
    int bi = blockIdx.y * 32;
    int bj = blockIdx.x * 32;
    int z = blockIdx.z;
    int tx = t & 7, ty = t >> 3;   // 8x8 micro grid
    int lrow = t >> 1;             // 0..31
    int lsel = t & 1;

    unsigned long long acc[4][2];
    #pragma unroll
    for (int r = 0; r < 4; r++) { acc[r][0] = 0ull; acc[r][1] = 0ull; }

    int kbeg = z * KCHUNK;
    for (int k0 = kbeg; k0 < kbeg + KCHUNK; k0 += 32) {
        float4 a[4], b[4];
        const float4* gA = (const float4*)(x + (size_t)(bi + lrow) * DE + k0);
        const float4* gB = (const float4*)(x + (size_t)(bj + lrow) * DE + k0);
        #pragma unroll
        for (int q = 0; q < 4; q++) {
            a[q] = gA[lsel + 2 * q];
            b[q] = gB[lsel + 2 * q];
        }
        __syncthreads();
        #pragma unroll
        for (int q = 0; q < 4; q++) {
            int c = 4 * (lsel + 2 * q);
            As[c + 0][lrow] = a[q].x; As[c + 1][lrow] = a[q].y;
            As[c + 2][lrow] = a[q].z; As[c + 3][lrow] = a[q].w;
            Bs[c + 0][lrow] = b[q].x; Bs[c + 1][lrow] = b[q].y;
            Bs[c + 2][lrow] = b[q].z; Bs[c + 3][lrow] = b[q].w;
        }
        __syncthreads();
        #pragma unroll
        for (int kk = 0; kk < 32; kk++) {
            float4 av = *(const float4*)&As[kk][4 * ty];
            ulonglong2 bv = *(const ulonglong2*)&Bs[kk][4 * tx];
            unsigned long long a0 = dupf(av.x), a1 = dupf(av.y);
            unsigned long long a2 = dupf(av.z), a3 = dupf(av.w);
            acc[0][0] = fma2(a0, bv.x, acc[0][0]); acc[0][1] = fma2(a0, bv.y, acc[0][1]);
            acc[1][0] = fma2(a1, bv.x, acc[1][0]); acc[1][1] = fma2(a1, bv.y, acc[1][1]);
            acc[2][0] = fma2(a2, bv.x, acc[2][0]); acc[2][1] = fma2(a2, bv.y, acc[2][1]);
            acc[3][0] = fma2(a3, bv.x, acc[3][0]); acc[3][1] = fma2(a3, bv.y, acc[3][1]);
        }
    }

    float* dst = g_part[z];
    #pragma unroll
    for (int r = 0; r < 4; r++) {
        float2 p0 = unpk(acc[r][0]);
        float2 p1 = unpk(acc[r][1]);
        float4 o;
        o.x = p0.x; o.y = p0.y; o.z = p1.x; o.w = p1.y;
        *(float4*)&dst[(size_t)(bi + 4 * ty + r) * NS + bj + 4 * tx] = o;
    }
}

// ---------------- kernel 3: per-anchor loss (fused prep) ----------------
// one block per anchor i, 128 threads; thread t owns columns [4t, 4t+4)
__global__ void __launch_bounds__(128) loss_kernel(const float* __restrict__ dist_raw,
                                                   const int* __restrict__ target) {
    __shared__ __align__(16) float bvals[NS];  // cos[i,j]+margin, or -1e30
    __shared__ float crow[NS];
    __shared__ float cps[NS];
    __shared__ int klist[NS];
    __shared__ float cls_pos[NC];
    __shared__ int kcnt, scount;
    __shared__ float red_s[4];
    __shared__ int red_n[4];

    int i = blockIdx.x;
    int t = threadIdx.x;

    if (t == 0) {
        kcnt = 0; scount = 0;
        float c = 0.f;
        cls_pos[0] = 0.f;
        #pragma unroll
        for (int q = 0; q < NC - 1; q++) {
            c += log1pf(expf(dist_raw[q]));  // softplus cumsum
            cls_pos[q + 1] = c;
        }
    }
    __syncthreads();

    // cos row i: sum 4 K-partials, scale by rn_i*rn_j
    float ri = g_rn[i];
    {
        size_t off = (size_t)i * NS + 4 * t;
        float4 p0 = *(const float4*)&g_part[0][off];
        float4 p1 = *(const float4*)&g_part[1][off];
        float4 p2 = *(const float4*)&g_part[2][off];
        float4 p3 = *(const float4*)&g_part[3][off];
        float4 rj = *(const float4*)&g_rn[4 * t];
        float4 c;
        c.x = (p0.x + p1.x + p2.x + p3.x) * ri * rj.x;
        c.y = (p0.y + p1.y + p2.y + p3.y) * ri * rj.y;
        c.z = (p0.z + p1.z + p2.z + p3.z) * ri * rj.z;
        c.w = (p0.w + p1.w + p2.w + p3.w) * ri * rj.w;
        *(float4*)&crow[4 * t] = c;
        int4 tg = *(const int4*)&target[4 * t];
        cps[4 * t + 0] = cls_pos[tg.x];
        cps[4 * t + 1] = cls_pos[tg.y];
        cps[4 * t + 2] = cls_pos[tg.z];
        cps[4 * t + 3] = cls_pos[tg.w];
    }
    __syncthreads();

    float cpi = cps[i];
    int myc = 0;
    #pragma unroll
    for (int q = 0; q < 4; q++) {
        int j = 4 * t + q;
        float m = fabsf(cpi - cps[j]);
        bool same = (m == 0.0f);  // class_pos strictly increasing -> equality iff same class
        bvals[j] = same ? -1e30f : (crow[j] + m);
        if (same) {
            myc++;
            if (j != i) klist[atomicAdd(&kcnt, 1)] = j;
        }
    }
    atomicAdd(&scount, myc);
    __syncthreads();

    int nk = kcnt;
    int negc = NS - scount;
    float inv = 1.0f / (float)(negc > 1 ? negc : 1);

    float lsum = 0.f;
    int lnz = 0;
    const float4* bv4 = (const float4*)bvals;
    for (int p = t; p < nk; p += 128) {
        float cik = crow[klist[p]];
        float acc0 = 0.f, acc1 = 0.f;
        #pragma unroll 8
        for (int jj = 0; jj < NS / 4; jj++) {
            float4 bv = bv4[jj];
            acc0 += fmaxf(bv.x - cik, 0.f) + fmaxf(bv.y - cik, 0.f);
            acc1 += fmaxf(bv.z - cik, 0.f) + fmaxf(bv.w - cik, 0.f);
        }
        float acc = acc0 + acc1;
        lsum += acc * inv;
        lnz += (acc != 0.f) ? 1 : 0;
    }

    // block reduce (4 warps)
    for (int o = 16; o > 0; o >>= 1) {
        lsum += __shfl_down_sync(0xffffffffu, lsum, o);
        lnz += __shfl_down_sync(0xffffffffu, lnz, o);
    }
    int wid = t >> 5, lid = t & 31;
    if (lid == 0) { red_s[wid] = lsum; red_n[wid] = lnz; }
    __syncthreads();
    if (t == 0) {
        g_psum[i] = red_s[0] + red_s[1] + red_s[2] + red_s[3];
        g_pnz[i] = red_n[0] + red_n[1] + red_n[2] + red_n[3];
    }
}

// ---------------- kernel 4: finalize ----------------
__global__ void __launch_bounds__(NS) fin_kernel(float* __restrict__ out) {
    __shared__ float ws[16];
    __shared__ int wn[16];
    int t = threadIdx.x;  // 512
    float s = g_psum[t];
    int n = g_pnz[t];
    for (int o = 16; o > 0; o >>= 1) {
        s += __shfl_down_sync(0xffffffffu, s, o);
        n += __shfl_down_sync(0xffffffffu, n, o);
    }
    int wid = t >> 5, lid = t & 31;
    if (lid == 0) { ws[wid] = s; wn[wid] = n; }
    __syncthreads();
    if (t == 0) {
        float S = 0.f; int N = 0;
        #pragma unroll
        for (int w = 0; w < 16; w++) { S += ws[w]; N += wn[w]; }
        out[0] = S / (float)(N > 1 ? N : 1);
    }
}

extern "C" void kernel_launch(void* const* d_in, const int* in_sizes, int n_in,
                              void* d_out, int out_size) {
    const float* pred = (const float*)d_in[0];   // [512, 512] f32
    const float* draw = (const float*)d_in[1];   // [4] f32
    const int* target = (const int*)d_in[2];     // [512] i32
    float* out = (float*)d_out;

    norm_kernel<<<NS, 128>>>(pred);
    gemm_kernel<<<dim3(16, 16, KSPLIT), 64>>>(pred);
    loss_kernel<<<NS, 128>>>(draw, target);
    fin_kernel<<<1, NS>>>(out);
}